// round 3
// baseline (speedup 1.0000x reference)
#include <cuda_runtime.h>
#include <math.h>
#include <stdint.h>

#define NN   40000
#define NP   40064          // 313 * 128, padded
#define EE   640000
#define FIN  33
#define HH   128
#define LL   8
#define ALPHA 0.1f

// ---------------- scratch (no allocation allowed) ----------------
__device__ float g_x0[NP * HH];
__device__ float g_xc[NP * HH];
__device__ float g_xx[NP * HH];   // zero-init; tail rows never written -> stay 0
__device__ int   g_rowptr[NN + 1];
__device__ int   g_off[NN];
__device__ int   g_cnt[NN];
__device__ int   g_cols[EE];
__device__ float g_w[EE];

__device__ __forceinline__ uint32_t f2tf32(float f) {
    uint32_t o;
    asm("cvt.rna.tf32.f32 %0, %1;" : "=r"(o) : "f"(f));
    return o;
}

// ---------------- input projection: x0 = relu(x @ W_in^T + b_in) ----------------
__global__ void input_proj_kernel(const float* __restrict__ x,
                                  const float* __restrict__ Win,
                                  const float* __restrict__ bin) {
    __shared__ float sW[HH * FIN];
    __shared__ float sx[FIN];
    int tid = threadIdx.x;
    for (int i = tid; i < HH * FIN; i += 128) sW[i] = Win[i];
    float b = bin[tid];
    int row0 = blockIdx.x * 32;
    for (int r = 0; r < 32; r++) {
        int row = row0 + r;
        __syncthreads();
        if (tid < FIN) sx[tid] = x[row * FIN + tid];
        __syncthreads();
        float s = b;
#pragma unroll
        for (int f = 0; f < FIN; f++) s += sW[tid * FIN + f] * sx[f];
        s = fmaxf(s, 0.0f);
        g_x0[row * HH + tid] = s;
        g_xc[row * HH + tid] = s;
    }
}

// ---------------- CSR build ----------------
__global__ void zero_cnt_kernel() {
    int i = blockIdx.x * blockDim.x + threadIdx.x;
    if (i < NN) g_cnt[i] = 0;
}
__global__ void count_kernel(const int* __restrict__ er) {
    int e = blockIdx.x * blockDim.x + threadIdx.x;
    if (e < EE) atomicAdd(&g_cnt[er[e]], 1);
}

// fast single-block scan: 1024 threads x 40-row chunks
__global__ void scan_kernel() {
    __shared__ int wsum[32];
    const int CH = 40;
    int tid = threadIdx.x;
    int base = tid * CH;
    int sum = 0;
#pragma unroll 8
    for (int i = 0; i < CH; i++) {
        int idx = base + i;
        if (idx < NN) sum += g_cnt[idx];
    }
    int lane = tid & 31, wid = tid >> 5;
    int inc = sum;
#pragma unroll
    for (int o = 1; o < 32; o <<= 1) {
        int t = __shfl_up_sync(0xFFFFFFFFu, inc, o);
        if (lane >= o) inc += t;
    }
    if (lane == 31) wsum[wid] = inc;
    __syncthreads();
    if (wid == 0) {
        int v = wsum[lane];
#pragma unroll
        for (int o = 1; o < 32; o <<= 1) {
            int t = __shfl_up_sync(0xFFFFFFFFu, v, o);
            if (lane >= o) v += t;
        }
        wsum[lane] = v;
    }
    __syncthreads();
    int off = (inc - sum) + (wid ? wsum[wid - 1] : 0);
    if (tid == 1023) g_rowptr[NN] = off + sum;
#pragma unroll 8
    for (int i = 0; i < CH; i++) {
        int idx = base + i;
        if (idx < NN) {
            g_rowptr[idx] = off;
            g_off[idx] = off;
            off += g_cnt[idx];
        }
    }
}

__global__ void scatter_kernel(const int* __restrict__ er,
                               const int* __restrict__ ec,
                               const float* __restrict__ ew) {
    int e = blockIdx.x * blockDim.x + threadIdx.x;
    if (e < EE) {
        int r = er[e];
        int p = atomicAdd(&g_off[r], 1);
        g_cols[p] = ec[e];
        g_w[p] = ew[e];
    }
}

// ---------------- SpMM + alpha combine: xx = 0.9 * (A @ xc) + 0.1 * x0 ----------------
__global__ void spmm_kernel() {
    int gt = blockIdx.x * blockDim.x + threadIdx.x;
    int row = gt >> 5;
    int lane = threadIdx.x & 31;
    if (row >= NN) return;
    int s = g_rowptr[row];
    int e = g_rowptr[row + 1];
    float4 acc = make_float4(0.f, 0.f, 0.f, 0.f);
    const float4* xc4 = (const float4*)g_xc;
    for (int i = s; i < e; i++) {
        int c = g_cols[i];
        float w = g_w[i];
        float4 v = xc4[c * 32 + lane];
        acc.x += w * v.x; acc.y += w * v.y; acc.z += w * v.z; acc.w += w * v.w;
    }
    float4 x0v = ((const float4*)g_x0)[row * 32 + lane];
    float4 o;
    o.x = (1.0f - ALPHA) * acc.x + ALPHA * x0v.x;
    o.y = (1.0f - ALPHA) * acc.y + ALPHA * x0v.y;
    o.z = (1.0f - ALPHA) * acc.z + ALPHA * x0v.z;
    o.w = (1.0f - ALPHA) * acc.w + ALPHA * x0v.w;
    ((float4*)g_xx)[row * 32 + lane] = o;
}

// ---------------- layer GEMM (mma.sync tf32) + GCNII epilogue ----------------
// CTA: 256 threads = 8 warps (4 M x 2 N). CTA tile M=128, N=128, K=128.
// Warp tile 32x64 via m16n8k8 tf32 mma (2 m-tiles x 8 n-tiles).
// Smem: As[k][m], Bs[k][n], BK=16, stride 136 floats, double-buffered.
#define BK   16
#define SSTR 136
#define SKT  (BK * SSTR)      // floats per buffer

__global__ void __launch_bounds__(256) layer_mma_kernel(const float* __restrict__ W,
                                                        float beta) {
    __shared__ float As[2 * SKT];
    __shared__ float Bs[2 * SKT];

    int tid = threadIdx.x;
    int wid = tid >> 5, lane = tid & 31;
    int wm = wid >> 1, wn = wid & 1;
    int m0 = wm * 32, n0 = wn * 64;
    int gr = lane >> 2, gc = lane & 3;
    int r0 = blockIdx.x * 128;

    const float* Ag = g_xx + (size_t)r0 * HH;

    float acc[2][8][4];
#pragma unroll
    for (int t = 0; t < 2; t++)
#pragma unroll
        for (int j = 0; j < 8; j++)
#pragma unroll
            for (int q = 0; q < 4; q++) acc[t][j][q] = 0.f;

    // chunk loader: A[128][BK] transposed into As[k][m]; B = W[k][n] into Bs[k][n]
    auto load_chunk = [&](int c, int buf) {
        float* Ab = As + buf * SKT;
        const float* Agc = Ag + c * BK;
#pragma unroll
        for (int i = 0; i < 2; i++) {
            int idx = tid + i * 256;       // 0..511
            int m = idx >> 2, k4 = idx & 3;
            float4 v = *(const float4*)&Agc[m * HH + k4 * 4];
            Ab[(k4 * 4 + 0) * SSTR + m] = __uint_as_float(f2tf32(v.x));
            Ab[(k4 * 4 + 1) * SSTR + m] = __uint_as_float(f2tf32(v.y));
            Ab[(k4 * 4 + 2) * SSTR + m] = __uint_as_float(f2tf32(v.z));
            Ab[(k4 * 4 + 3) * SSTR + m] = __uint_as_float(f2tf32(v.w));
        }
        float* Bb = Bs + buf * SKT;
        const float* Wc_ = W + c * BK * HH;
#pragma unroll
        for (int i = 0; i < 2; i++) {
            int idx = tid + i * 256;       // 0..511
            int k = idx >> 5, n4 = idx & 31;
            float4 v = *(const float4*)&Wc_[k * HH + n4 * 4];
            uint4 o;
            o.x = f2tf32(v.x); o.y = f2tf32(v.y);
            o.z = f2tf32(v.z); o.w = f2tf32(v.w);
            *(uint4*)&Bb[k * SSTR + n4 * 4] = o;
        }
    };

    load_chunk(0, 0);
    __syncthreads();

    const int NCH = HH / BK;   // 8
#pragma unroll
    for (int c = 0; c < NCH; c++) {
        int cur = c & 1;
        if (c < NCH - 1) load_chunk(c + 1, cur ^ 1);
        const float* Ac = As + cur * SKT;
        const float* Bc = Bs + cur * SKT;
#pragma unroll
        for (int ks = 0; ks < BK / 8; ks++) {
            int kk = ks * 8;
            uint32_t a[2][4];
#pragma unroll
            for (int t = 0; t < 2; t++) {
                const float* ap = &Ac[(kk + gc) * SSTR + m0 + t * 16 + gr];
                a[t][0] = __float_as_uint(ap[0]);
                a[t][1] = __float_as_uint(ap[8]);
                a[t][2] = __float_as_uint(ap[4 * SSTR]);
                a[t][3] = __float_as_uint(ap[4 * SSTR + 8]);
            }
            uint32_t b[8][2];
#pragma unroll
            for (int j = 0; j < 8; j++) {
                const float* bp = &Bc[(kk + gc) * SSTR + n0 + j * 8 + gr];
                b[j][0] = __float_as_uint(bp[0]);
                b[j][1] = __float_as_uint(bp[4 * SSTR]);
            }
#pragma unroll
            for (int t = 0; t < 2; t++)
#pragma unroll
                for (int j = 0; j < 8; j++) {
                    asm volatile(
                        "mma.sync.aligned.m16n8k8.row.col.f32.tf32.tf32.f32 "
                        "{%0,%1,%2,%3}, {%4,%5,%6,%7}, {%8,%9}, {%0,%1,%2,%3};"
                        : "+f"(acc[t][j][0]), "+f"(acc[t][j][1]),
                          "+f"(acc[t][j][2]), "+f"(acc[t][j][3])
                        : "r"(a[t][0]), "r"(a[t][1]), "r"(a[t][2]), "r"(a[t][3]),
                          "r"(b[j][0]), "r"(b[j][1]));
                }
        }
        __syncthreads();
    }

    // epilogue: xc += relu((1-beta)*xx + beta*acc)
    float omb = 1.0f - beta;
#pragma unroll
    for (int t = 0; t < 2; t++) {
        int rr = r0 + m0 + t * 16 + gr;
#pragma unroll
        for (int j = 0; j < 8; j++) {
            int col = n0 + j * 8 + gc * 2;
            {
                const float2 xv = *(const float2*)&g_xx[(size_t)rr * HH + col];
                float2 cv = *(float2*)&g_xc[(size_t)rr * HH + col];
                cv.x += fmaxf(omb * xv.x + beta * acc[t][j][0], 0.f);
                cv.y += fmaxf(omb * xv.y + beta * acc[t][j][1], 0.f);
                *(float2*)&g_xc[(size_t)rr * HH + col] = cv;
            }
            {
                const float2 xv = *(const float2*)&g_xx[(size_t)(rr + 8) * HH + col];
                float2 cv = *(float2*)&g_xc[(size_t)(rr + 8) * HH + col];
                cv.x += fmaxf(omb * xv.x + beta * acc[t][j][2], 0.f);
                cv.y += fmaxf(omb * xv.y + beta * acc[t][j][3], 0.f);
                *(float2*)&g_xc[(size_t)(rr + 8) * HH + col] = cv;
            }
        }
    }
}

// ---------------- output projection: out = xc @ W_out^T + b_out ----------------
__global__ void out_proj_kernel(const float* __restrict__ Wout,
                                const float* __restrict__ bout,
                                float* __restrict__ out) {
    int gt = blockIdx.x * blockDim.x + threadIdx.x;
    int row = gt >> 5;
    int lane = threadIdx.x & 31;
    if (row >= NN) return;
    float4 v = ((const float4*)g_xc)[row * 32 + lane];
#pragma unroll
    for (int c = 0; c < 3; c++) {
        float4 w = *(const float4*)&Wout[c * HH + lane * 4];
        float s = v.x * w.x + v.y * w.y + v.z * w.z + v.w * w.w;
#pragma unroll
        for (int o = 16; o; o >>= 1) s += __shfl_down_sync(0xFFFFFFFFu, s, o);
        if (lane == 0) out[row * 3 + c] = s + bout[c];
    }
}

extern "C" void kernel_launch(void* const* d_in, const int* in_sizes, int n_in,
                              void* d_out, int out_size) {
    const float* x    = (const float*)d_in[0];
    const int*   er   = (const int*)d_in[1];
    const int*   ec   = (const int*)d_in[2];
    const float* ew   = (const float*)d_in[3];
    const float* Win  = (const float*)d_in[4];
    const float* bin  = (const float*)d_in[5];
    const float* Wout = (const float*)d_in[6];
    const float* bout = (const float*)d_in[7];
    const float* Wc   = (const float*)d_in[8];
    float* out = (float*)d_out;

    input_proj_kernel<<<NN / 32, 128>>>(x, Win, bin);
    zero_cnt_kernel<<<(NN + 255) / 256, 256>>>();
    count_kernel<<<(EE + 255) / 256, 256>>>(er);
    scan_kernel<<<1, 1024>>>();
    scatter_kernel<<<(EE + 255) / 256, 256>>>(er, ec, ew);

    for (int l = 0; l < LL; l++) {
        float beta = logf(0.5f / (float)(l + 1) + 1.0f);
        spmm_kernel<<<(NN * 32 + 255) / 256, 256>>>();
        layer_mma_kernel<<<NP / 128, 256>>>(Wc + (size_t)l * HH * HH, beta);
    }

    out_proj_kernel<<<(NN * 32 + 255) / 256, 256>>>(Wout, bout, out);
}